// round 1
// baseline (speedup 1.0000x reference)
#include <cuda_runtime.h>
#include <math.h>

#define DIM 4096
#define BSZ 1024
#define NW  12

#define BM 128
#define BN 64
#define BK 8
#define NT (DIM / BK)

// Scratch (allocation-free rule: device globals)
__device__ float g_s2_re[DIM * BSZ];   // permuted intermediate state, [k][b]
__device__ float g_s2_im[DIM * BSZ];
__device__ int   g_invperm[DIM];
__device__ float g_norm[BSZ];

// ---------------------------------------------------------------------------
// invperm: reference builds perm via reversed CNOT-ring; we invert by scatter.
// ---------------------------------------------------------------------------
__global__ void perm_kernel() {
    int j = blockIdx.x * blockDim.x + threadIdx.x;
    if (j >= DIM) return;
    int idx = j;
#pragma unroll
    for (int i = NW - 1; i >= 0; --i) {
        int c = i;
        int t = (i + 1) % NW;
        int cbit = (idx >> (NW - 1 - c)) & 1;
        idx ^= cbit << (NW - 1 - t);
    }
    // idx == perm[j]  =>  invperm[perm[j]] = j
    g_invperm[idx] = j;
}

// ---------------------------------------------------------------------------
// Row norms of x (normalization deferred to final epilogue)
// ---------------------------------------------------------------------------
__global__ void norm_kernel(const float* __restrict__ x) {
    int b = blockIdx.x;
    const float4* xr = (const float4*)(x + (size_t)b * DIM);
    float s = 0.f;
    for (int i = threadIdx.x; i < DIM / 4; i += blockDim.x) {
        float4 v = xr[i];
        s += v.x * v.x + v.y * v.y + v.z * v.z + v.w * v.w;
    }
    __shared__ float red[4];
#pragma unroll
    for (int o = 16; o > 0; o >>= 1) s += __shfl_down_sync(0xffffffffu, s, o);
    if ((threadIdx.x & 31) == 0) red[threadIdx.x >> 5] = s;
    __syncthreads();
    if (threadIdx.x == 0) {
        float tot = red[0] + red[1] + red[2] + red[3];
        g_norm[b] = sqrtf(tot);
    }
}

// ---------------------------------------------------------------------------
// GEMM1 (dual): S1_re/S1_im[i,b] = sum_j U_re/U_im[i,j] * x[b,j]
// Epilogue scatters row i -> invperm[i] so scratch holds the permuted state.
// A: row-major [M,K]; B: x row-major [N,K] (both K-contiguous, "NT" GEMM).
// ---------------------------------------------------------------------------
__global__ __launch_bounds__(256, 2)
void gemm1_kernel(const float* __restrict__ Ure,
                  const float* __restrict__ Uim,
                  const float* __restrict__ X) {
    __shared__ float As_re[2][BK][BM];
    __shared__ float As_im[2][BK][BM];
    __shared__ float Bs[2][BK][BN];

    const int tid = threadIdx.x;
    const int m0 = blockIdx.y * BM;
    const int n0 = blockIdx.x * BN;
    const int tx = tid & 15;   // n direction
    const int ty = tid >> 4;   // m direction

    // A tile loads: 128 rows x 8 k, float4 each, 2 threads/row
    const int ar = tid >> 1;
    const int ac = (tid & 1) << 2;
    // B tile loads: 64 rows x 8 k (tid < 128)
    const int br = (tid >> 1) & 63;
    const int bc = (tid & 1) << 2;

    const float* pAre = Ure + (size_t)(m0 + ar) * DIM + ac;
    const float* pAim = Uim + (size_t)(m0 + ar) * DIM + ac;
    const float* pB   = X   + (size_t)(n0 + br) * DIM + bc;

    float4 ra, ri, rb;
    ra = *(const float4*)pAre;
    ri = *(const float4*)pAim;
    if (tid < 128) rb = *(const float4*)pB;

    As_re[0][ac + 0][ar] = ra.x; As_re[0][ac + 1][ar] = ra.y;
    As_re[0][ac + 2][ar] = ra.z; As_re[0][ac + 3][ar] = ra.w;
    As_im[0][ac + 0][ar] = ri.x; As_im[0][ac + 1][ar] = ri.y;
    As_im[0][ac + 2][ar] = ri.z; As_im[0][ac + 3][ar] = ri.w;
    if (tid < 128) {
        Bs[0][bc + 0][br] = rb.x; Bs[0][bc + 1][br] = rb.y;
        Bs[0][bc + 2][br] = rb.z; Bs[0][bc + 3][br] = rb.w;
    }
    __syncthreads();

    float cr[8][4];
    float ci[8][4];
#pragma unroll
    for (int i = 0; i < 8; ++i)
#pragma unroll
        for (int j = 0; j < 4; ++j) { cr[i][j] = 0.f; ci[i][j] = 0.f; }

    for (int t = 0; t < NT; ++t) {
        const int cur = t & 1;
        if (t + 1 < NT) {
            const int ko = (t + 1) * BK;
            ra = *(const float4*)(pAre + ko);
            ri = *(const float4*)(pAim + ko);
            if (tid < 128) rb = *(const float4*)(pB + ko);
        }
#pragma unroll
        for (int k = 0; k < BK; ++k) {
            float a[8], ai[8], b[4];
            *(float4*)&a[0]  = *(const float4*)&As_re[cur][k][ty * 8];
            *(float4*)&a[4]  = *(const float4*)&As_re[cur][k][ty * 8 + 4];
            *(float4*)&ai[0] = *(const float4*)&As_im[cur][k][ty * 8];
            *(float4*)&ai[4] = *(const float4*)&As_im[cur][k][ty * 8 + 4];
            *(float4*)&b[0]  = *(const float4*)&Bs[cur][k][tx * 4];
#pragma unroll
            for (int i = 0; i < 8; ++i)
#pragma unroll
                for (int j = 0; j < 4; ++j) {
                    cr[i][j] = fmaf(a[i],  b[j], cr[i][j]);
                    ci[i][j] = fmaf(ai[i], b[j], ci[i][j]);
                }
        }
        if (t + 1 < NT) {
            const int nb = cur ^ 1;
            As_re[nb][ac + 0][ar] = ra.x; As_re[nb][ac + 1][ar] = ra.y;
            As_re[nb][ac + 2][ar] = ra.z; As_re[nb][ac + 3][ar] = ra.w;
            As_im[nb][ac + 0][ar] = ri.x; As_im[nb][ac + 1][ar] = ri.y;
            As_im[nb][ac + 2][ar] = ri.z; As_im[nb][ac + 3][ar] = ri.w;
            if (tid < 128) {
                Bs[nb][bc + 0][br] = rb.x; Bs[nb][bc + 1][br] = rb.y;
                Bs[nb][bc + 2][br] = rb.z; Bs[nb][bc + 3][br] = rb.w;
            }
        }
        __syncthreads();
    }

#pragma unroll
    for (int i = 0; i < 8; ++i) {
        const int gm = m0 + ty * 8 + i;
        const int row = g_invperm[gm];
        float* pr = &g_s2_re[(size_t)row * BSZ + n0 + tx * 4];
        float* pi = &g_s2_im[(size_t)row * BSZ + n0 + tx * 4];
        *(float4*)pr = make_float4(cr[i][0], cr[i][1], cr[i][2], cr[i][3]);
        *(float4*)pi = make_float4(ci[i][0], ci[i][1], ci[i][2], ci[i][3]);
    }
}

// ---------------------------------------------------------------------------
// GEMM2 (complex): out[b,i] = |sum_k (U1_re + i U1_im)[i,k] * s2[k,b]| / norm[b]
// A: row-major [M,K]; B: scratch [K,N] (N-contiguous, "NN" GEMM).
// ---------------------------------------------------------------------------
__global__ __launch_bounds__(256, 2)
void gemm2_kernel(const float* __restrict__ U1re,
                  const float* __restrict__ U1im,
                  float* __restrict__ out) {
    __shared__ float As_re[2][BK][BM];
    __shared__ float As_im[2][BK][BM];
    __shared__ float Bs_re[2][BK][BN];
    __shared__ float Bs_im[2][BK][BN];

    const int tid = threadIdx.x;
    const int m0 = blockIdx.y * BM;
    const int n0 = blockIdx.x * BN;
    const int tx = tid & 15;
    const int ty = tid >> 4;

    const int ar = tid >> 1;
    const int ac = (tid & 1) << 2;

    // B tile: 8 k-rows x 64 n, re by tid<128 / im by tid>=128
    const int t2 = tid & 127;
    const int bk = t2 >> 4;
    const int bn = (t2 & 15) << 2;

    const float* pAre = U1re + (size_t)(m0 + ar) * DIM + ac;
    const float* pAim = U1im + (size_t)(m0 + ar) * DIM + ac;
    const float* pB = (tid < 128 ? g_s2_re : g_s2_im) + (size_t)bk * BSZ + n0 + bn;

    float4 ra, ri, rb;
    ra = *(const float4*)pAre;
    ri = *(const float4*)pAim;
    rb = *(const float4*)pB;

    As_re[0][ac + 0][ar] = ra.x; As_re[0][ac + 1][ar] = ra.y;
    As_re[0][ac + 2][ar] = ra.z; As_re[0][ac + 3][ar] = ra.w;
    As_im[0][ac + 0][ar] = ri.x; As_im[0][ac + 1][ar] = ri.y;
    As_im[0][ac + 2][ar] = ri.z; As_im[0][ac + 3][ar] = ri.w;
    if (tid < 128) *(float4*)&Bs_re[0][bk][bn] = rb;
    else           *(float4*)&Bs_im[0][bk][bn] = rb;
    __syncthreads();

    float cr[8][4];
    float ci[8][4];
#pragma unroll
    for (int i = 0; i < 8; ++i)
#pragma unroll
        for (int j = 0; j < 4; ++j) { cr[i][j] = 0.f; ci[i][j] = 0.f; }

    for (int t = 0; t < NT; ++t) {
        const int cur = t & 1;
        if (t + 1 < NT) {
            const int ko = (t + 1) * BK;
            ra = *(const float4*)(pAre + ko);
            ri = *(const float4*)(pAim + ko);
            rb = *(const float4*)(pB + (size_t)ko * BSZ);
        }
#pragma unroll
        for (int k = 0; k < BK; ++k) {
            float a[8], ai[8], br_[4], bi_[4];
            *(float4*)&a[0]   = *(const float4*)&As_re[cur][k][ty * 8];
            *(float4*)&a[4]   = *(const float4*)&As_re[cur][k][ty * 8 + 4];
            *(float4*)&ai[0]  = *(const float4*)&As_im[cur][k][ty * 8];
            *(float4*)&ai[4]  = *(const float4*)&As_im[cur][k][ty * 8 + 4];
            *(float4*)&br_[0] = *(const float4*)&Bs_re[cur][k][tx * 4];
            *(float4*)&bi_[0] = *(const float4*)&Bs_im[cur][k][tx * 4];
#pragma unroll
            for (int i = 0; i < 8; ++i)
#pragma unroll
                for (int j = 0; j < 4; ++j) {
                    cr[i][j] = fmaf(a[i],   br_[j], cr[i][j]);
                    cr[i][j] = fmaf(-ai[i], bi_[j], cr[i][j]);
                    ci[i][j] = fmaf(a[i],   bi_[j], ci[i][j]);
                    ci[i][j] = fmaf(ai[i],  br_[j], ci[i][j]);
                }
        }
        if (t + 1 < NT) {
            const int nb = cur ^ 1;
            As_re[nb][ac + 0][ar] = ra.x; As_re[nb][ac + 1][ar] = ra.y;
            As_re[nb][ac + 2][ar] = ra.z; As_re[nb][ac + 3][ar] = ra.w;
            As_im[nb][ac + 0][ar] = ri.x; As_im[nb][ac + 1][ar] = ri.y;
            As_im[nb][ac + 2][ar] = ri.z; As_im[nb][ac + 3][ar] = ri.w;
            if (tid < 128) *(float4*)&Bs_re[nb][bk][bn] = rb;
            else           *(float4*)&Bs_im[nb][bk][bn] = rb;
        }
        __syncthreads();
    }

    // epilogue: abs + deferred normalization, transposed write out[b, i]
#pragma unroll
    for (int j = 0; j < 4; ++j) {
        const int n = n0 + tx * 4 + j;
        const float inv = 1.0f / g_norm[n];
        float o[8];
#pragma unroll
        for (int i = 0; i < 8; ++i)
            o[i] = sqrtf(cr[i][j] * cr[i][j] + ci[i][j] * ci[i][j]) * inv;
        float* po = out + (size_t)n * DIM + m0 + ty * 8;
        *(float4*)po       = make_float4(o[0], o[1], o[2], o[3]);
        *(float4*)(po + 4) = make_float4(o[4], o[5], o[6], o[7]);
    }
}

// ---------------------------------------------------------------------------
extern "C" void kernel_launch(void* const* d_in, const int* in_sizes, int n_in,
                              void* d_out, int out_size) {
    const float* x     = (const float*)d_in[0];
    const float* U_re  = (const float*)d_in[1];
    const float* U_im  = (const float*)d_in[2];
    const float* U1_re = (const float*)d_in[3];
    const float* U1_im = (const float*)d_in[4];
    float* out = (float*)d_out;

    perm_kernel<<<DIM / 256, 256>>>();
    norm_kernel<<<BSZ, 128>>>(x);

    dim3 grid(BSZ / BN, DIM / BM);   // (16, 32)
    gemm1_kernel<<<grid, 256>>>(U_re, U_im, x);
    gemm2_kernel<<<grid, 256>>>(U1_re, U1_im, out);
}

// round 2
// speedup vs baseline: 1.0971x; 1.0971x over previous
#include <cuda_runtime.h>
#include <math.h>

#define DIM 4096
#define BSZ 1024
#define NW  12

#define BM 128
#define BN 64
#define BK 8
#define NT (DIM / BK)

typedef unsigned long long u64;

// ---- packed fp32x2 helpers (Blackwell-only; ptxas never auto-fuses these) ----
__device__ __forceinline__ u64 pack2(float lo, float hi) {
    u64 r; asm("mov.b64 %0, {%1, %2};" : "=l"(r) : "f"(lo), "f"(hi)); return r;
}
__device__ __forceinline__ u64 dup2(float v) { return pack2(v, v); }
__device__ __forceinline__ void unpack2(u64 v, float& lo, float& hi) {
    asm("mov.b64 {%0, %1}, %2;" : "=f"(lo), "=f"(hi) : "l"(v));
}
__device__ __forceinline__ void ffma2(u64& c, u64 a, u64 b) {
    asm("fma.rn.f32x2 %0, %1, %2, %0;" : "+l"(c) : "l"(a), "l"(b));
}

// Scratch (allocation-free rule: device globals)
__device__ float g_s2_re[DIM * BSZ];   // permuted intermediate state, [k][b]
__device__ float g_s2_im[DIM * BSZ];
__device__ int   g_invperm[DIM];
__device__ float g_norm[BSZ];

// ---------------------------------------------------------------------------
__global__ void perm_kernel() {
    int j = blockIdx.x * blockDim.x + threadIdx.x;
    if (j >= DIM) return;
    int idx = j;
#pragma unroll
    for (int i = NW - 1; i >= 0; --i) {
        int c = i;
        int t = (i + 1) % NW;
        int cbit = (idx >> (NW - 1 - c)) & 1;
        idx ^= cbit << (NW - 1 - t);
    }
    g_invperm[idx] = j;     // idx == perm[j]
}

// ---------------------------------------------------------------------------
__global__ void norm_kernel(const float* __restrict__ x) {
    int b = blockIdx.x;
    const float4* xr = (const float4*)(x + (size_t)b * DIM);
    float s = 0.f;
    for (int i = threadIdx.x; i < DIM / 4; i += blockDim.x) {
        float4 v = xr[i];
        s += v.x * v.x + v.y * v.y + v.z * v.z + v.w * v.w;
    }
    __shared__ float red[4];
#pragma unroll
    for (int o = 16; o > 0; o >>= 1) s += __shfl_down_sync(0xffffffffu, s, o);
    if ((threadIdx.x & 31) == 0) red[threadIdx.x >> 5] = s;
    __syncthreads();
    if (threadIdx.x == 0) {
        float tot = red[0] + red[1] + red[2] + red[3];
        g_norm[b] = sqrtf(tot);
    }
}

// ---------------------------------------------------------------------------
// GEMM1 (dual): S1_re/S1_im[i,b] = sum_j U_re/U_im[i,j] * x[b,j]
// Packed f32x2 along m. Scatter epilogue applies the CNOT-ring permutation.
// ---------------------------------------------------------------------------
__global__ __launch_bounds__(256, 2)
void gemm1_kernel(const float* __restrict__ Ure,
                  const float* __restrict__ Uim,
                  const float* __restrict__ X) {
    __shared__ __align__(16) float As_re[2][BK][BM];
    __shared__ __align__(16) float As_im[2][BK][BM];
    __shared__ __align__(16) float Bs[2][BK][BN];

    const int tid = threadIdx.x;
    const int m0 = blockIdx.y * BM;
    const int n0 = blockIdx.x * BN;
    const int tx = tid & 15;   // n direction
    const int ty = tid >> 4;   // m direction

    const int ar = tid >> 1;
    const int ac = (tid & 1) << 2;
    const int br = (tid >> 1) & 63;
    const int bc = (tid & 1) << 2;

    const float* pAre = Ure + (size_t)(m0 + ar) * DIM + ac;
    const float* pAim = Uim + (size_t)(m0 + ar) * DIM + ac;
    const float* pB   = X   + (size_t)(n0 + br) * DIM + bc;

    float4 ra, ri, rb;
    ra = *(const float4*)pAre;
    ri = *(const float4*)pAim;
    if (tid < 128) rb = *(const float4*)pB;

    As_re[0][ac + 0][ar] = ra.x; As_re[0][ac + 1][ar] = ra.y;
    As_re[0][ac + 2][ar] = ra.z; As_re[0][ac + 3][ar] = ra.w;
    As_im[0][ac + 0][ar] = ri.x; As_im[0][ac + 1][ar] = ri.y;
    As_im[0][ac + 2][ar] = ri.z; As_im[0][ac + 3][ar] = ri.w;
    if (tid < 128) {
        Bs[0][bc + 0][br] = rb.x; Bs[0][bc + 1][br] = rb.y;
        Bs[0][bc + 2][br] = rb.z; Bs[0][bc + 3][br] = rb.w;
    }
    __syncthreads();

    // packed accumulators: [i2][j], i2 = m-pair index
    u64 c2r[4][4], c2i[4][4];
#pragma unroll
    for (int q = 0; q < 4; ++q)
#pragma unroll
        for (int j = 0; j < 4; ++j) { c2r[q][j] = 0ull; c2i[q][j] = 0ull; }

    for (int t = 0; t < NT; ++t) {
        const int cur = t & 1;
        if (t + 1 < NT) {
            const int ko = (t + 1) * BK;
            ra = *(const float4*)(pAre + ko);
            ri = *(const float4*)(pAim + ko);
            if (tid < 128) rb = *(const float4*)(pB + ko);
        }
#pragma unroll
        for (int k = 0; k < BK; ++k) {
            u64 a2r[4], a2i[4];
#pragma unroll
            for (int q = 0; q < 4; ++q) {
                a2r[q] = *(const u64*)&As_re[cur][k][ty * 8 + 2 * q];
                a2i[q] = *(const u64*)&As_im[cur][k][ty * 8 + 2 * q];
            }
            float4 b4 = *(const float4*)&Bs[cur][k][tx * 4];
            const float bs[4] = {b4.x, b4.y, b4.z, b4.w};
#pragma unroll
            for (int j = 0; j < 4; ++j) {
                u64 bd = dup2(bs[j]);
#pragma unroll
                for (int q = 0; q < 4; ++q) {
                    ffma2(c2r[q][j], a2r[q], bd);
                    ffma2(c2i[q][j], a2i[q], bd);
                }
            }
        }
        if (t + 1 < NT) {
            const int nb = cur ^ 1;
            As_re[nb][ac + 0][ar] = ra.x; As_re[nb][ac + 1][ar] = ra.y;
            As_re[nb][ac + 2][ar] = ra.z; As_re[nb][ac + 3][ar] = ra.w;
            As_im[nb][ac + 0][ar] = ri.x; As_im[nb][ac + 1][ar] = ri.y;
            As_im[nb][ac + 2][ar] = ri.z; As_im[nb][ac + 3][ar] = ri.w;
            if (tid < 128) {
                Bs[nb][bc + 0][br] = rb.x; Bs[nb][bc + 1][br] = rb.y;
                Bs[nb][bc + 2][br] = rb.z; Bs[nb][bc + 3][br] = rb.w;
            }
        }
        __syncthreads();
    }

#pragma unroll
    for (int q = 0; q < 4; ++q) {
        float r0[4], r1[4], i0[4], i1[4];
#pragma unroll
        for (int j = 0; j < 4; ++j) {
            unpack2(c2r[q][j], r0[j], r1[j]);
            unpack2(c2i[q][j], i0[j], i1[j]);
        }
        const int gm0 = m0 + ty * 8 + 2 * q;
        const int row0 = g_invperm[gm0];
        const int row1 = g_invperm[gm0 + 1];
        *(float4*)&g_s2_re[(size_t)row0 * BSZ + n0 + tx * 4] = make_float4(r0[0], r0[1], r0[2], r0[3]);
        *(float4*)&g_s2_im[(size_t)row0 * BSZ + n0 + tx * 4] = make_float4(i0[0], i0[1], i0[2], i0[3]);
        *(float4*)&g_s2_re[(size_t)row1 * BSZ + n0 + tx * 4] = make_float4(r1[0], r1[1], r1[2], r1[3]);
        *(float4*)&g_s2_im[(size_t)row1 * BSZ + n0 + tx * 4] = make_float4(i1[0], i1[1], i1[2], i1[3]);
    }
}

// ---------------------------------------------------------------------------
// GEMM2 (complex): out[b,i] = |sum_k (U1_re + i U1_im)[i,k] * s2[k,b]| / norm[b]
// Packed f32x2 along m.
// ---------------------------------------------------------------------------
__global__ __launch_bounds__(256, 2)
void gemm2_kernel(const float* __restrict__ U1re,
                  const float* __restrict__ U1im,
                  float* __restrict__ out) {
    __shared__ __align__(16) float As_re[2][BK][BM];
    __shared__ __align__(16) float As_im[2][BK][BM];
    __shared__ __align__(16) float Bs_re[2][BK][BN];
    __shared__ __align__(16) float Bs_im[2][BK][BN];

    const int tid = threadIdx.x;
    const int m0 = blockIdx.y * BM;
    const int n0 = blockIdx.x * BN;
    const int tx = tid & 15;
    const int ty = tid >> 4;

    const int ar = tid >> 1;
    const int ac = (tid & 1) << 2;

    const int t2 = tid & 127;
    const int bk = t2 >> 4;
    const int bn = (t2 & 15) << 2;

    const float* pAre = U1re + (size_t)(m0 + ar) * DIM + ac;
    const float* pAim = U1im + (size_t)(m0 + ar) * DIM + ac;
    const float* pB = (tid < 128 ? g_s2_re : g_s2_im) + (size_t)bk * BSZ + n0 + bn;

    float4 ra, ri, rb;
    ra = *(const float4*)pAre;
    ri = *(const float4*)pAim;
    rb = *(const float4*)pB;

    As_re[0][ac + 0][ar] = ra.x; As_re[0][ac + 1][ar] = ra.y;
    As_re[0][ac + 2][ar] = ra.z; As_re[0][ac + 3][ar] = ra.w;
    As_im[0][ac + 0][ar] = ri.x; As_im[0][ac + 1][ar] = ri.y;
    As_im[0][ac + 2][ar] = ri.z; As_im[0][ac + 3][ar] = ri.w;
    if (tid < 128) *(float4*)&Bs_re[0][bk][bn] = rb;
    else           *(float4*)&Bs_im[0][bk][bn] = rb;
    __syncthreads();

    u64 c2r[4][4], c2i[4][4];
#pragma unroll
    for (int q = 0; q < 4; ++q)
#pragma unroll
        for (int j = 0; j < 4; ++j) { c2r[q][j] = 0ull; c2i[q][j] = 0ull; }

    for (int t = 0; t < NT; ++t) {
        const int cur = t & 1;
        if (t + 1 < NT) {
            const int ko = (t + 1) * BK;
            ra = *(const float4*)(pAre + ko);
            ri = *(const float4*)(pAim + ko);
            rb = *(const float4*)(pB + (size_t)ko * BSZ);
        }
#pragma unroll
        for (int k = 0; k < BK; ++k) {
            u64 a2r[4], a2i[4];
#pragma unroll
            for (int q = 0; q < 4; ++q) {
                a2r[q] = *(const u64*)&As_re[cur][k][ty * 8 + 2 * q];
                a2i[q] = *(const u64*)&As_im[cur][k][ty * 8 + 2 * q];
            }
            float4 br4 = *(const float4*)&Bs_re[cur][k][tx * 4];
            float4 bi4 = *(const float4*)&Bs_im[cur][k][tx * 4];
            const float brs[4] = {br4.x, br4.y, br4.z, br4.w};
            const float bis[4] = {bi4.x, bi4.y, bi4.z, bi4.w};
#pragma unroll
            for (int j = 0; j < 4; ++j) {
                u64 brd  = dup2(brs[j]);
                u64 bid  = dup2(bis[j]);
                u64 bidn = dup2(-bis[j]);
#pragma unroll
                for (int q = 0; q < 4; ++q) {
                    ffma2(c2r[q][j], a2r[q], brd);
                    ffma2(c2r[q][j], a2i[q], bidn);
                    ffma2(c2i[q][j], a2r[q], bid);
                    ffma2(c2i[q][j], a2i[q], brd);
                }
            }
        }
        if (t + 1 < NT) {
            const int nb = cur ^ 1;
            As_re[nb][ac + 0][ar] = ra.x; As_re[nb][ac + 1][ar] = ra.y;
            As_re[nb][ac + 2][ar] = ra.z; As_re[nb][ac + 3][ar] = ra.w;
            As_im[nb][ac + 0][ar] = ri.x; As_im[nb][ac + 1][ar] = ri.y;
            As_im[nb][ac + 2][ar] = ri.z; As_im[nb][ac + 3][ar] = ri.w;
            if (tid < 128) *(float4*)&Bs_re[nb][bk][bn] = rb;
            else           *(float4*)&Bs_im[nb][bk][bn] = rb;
        }
        __syncthreads();
    }

    // epilogue: abs + deferred normalization, transposed write out[b, i]
#pragma unroll
    for (int j = 0; j < 4; ++j) {
        const int n = n0 + tx * 4 + j;
        const float inv = 1.0f / g_norm[n];
        float o[8];
#pragma unroll
        for (int q = 0; q < 4; ++q) {
            float rl, rh, il, ih;
            unpack2(c2r[q][j], rl, rh);
            unpack2(c2i[q][j], il, ih);
            o[2 * q]     = sqrtf(rl * rl + il * il) * inv;
            o[2 * q + 1] = sqrtf(rh * rh + ih * ih) * inv;
        }
        float* po = out + (size_t)n * DIM + m0 + ty * 8;
        *(float4*)po       = make_float4(o[0], o[1], o[2], o[3]);
        *(float4*)(po + 4) = make_float4(o[4], o[5], o[6], o[7]);
    }
}

// ---------------------------------------------------------------------------
extern "C" void kernel_launch(void* const* d_in, const int* in_sizes, int n_in,
                              void* d_out, int out_size) {
    const float* x     = (const float*)d_in[0];
    const float* U_re  = (const float*)d_in[1];
    const float* U_im  = (const float*)d_in[2];
    const float* U1_re = (const float*)d_in[3];
    const float* U1_im = (const float*)d_in[4];
    float* out = (float*)d_out;

    perm_kernel<<<DIM / 256, 256>>>();
    norm_kernel<<<BSZ, 128>>>(x);

    dim3 grid(BSZ / BN, DIM / BM);   // (16, 32)
    gemm1_kernel<<<grid, 256>>>(U_re, U_im, x);
    gemm2_kernel<<<grid, 256>>>(U1_re, U1_im, out);
}